// round 1
// baseline (speedup 1.0000x reference)
#include <cuda_runtime.h>
#include <math.h>
#include <stdint.h>

#define Nn 50000
#define Ee 1600000
#define EP 1650000          // Ee + Nn self loops
#define CACHE_MAX 128       // per-node cached exp slots (deg ~ Poisson(33); P(deg>128) ~ 0)

// ---------------- device scratch (static, no allocation) ----------------
__device__ int   g_deg[Nn];
__device__ int   g_off[Nn];
__device__ int   g_rowptr[Nn + 1];
__device__ int   g_ssrc[EP];
__device__ int   g_seid[EP];
__device__ float g_h [Nn * 128];
__device__ float g_x1[Nn * 128];
__device__ float g_h2[Nn * 32];
__device__ float g_asrc[Nn * 4];
__device__ float g_adst[Nn * 4];
__device__ float g_as2[Nn];
__device__ float g_ad2[Nn];

// ---------------- helpers ----------------
__device__ __forceinline__ float lrelu(float x) { return x > 0.f ? x : 0.2f * x; }

// FMA-only exp (no MUFU). Valid for x <= ~30; clamps below -80 (result ~0).
__device__ __forceinline__ float fexp(float x) {
    x = fmaxf(x, -80.0f);
    float t = x * 1.4426950408889634f;
    float r = t + 12582912.0f;                 // round-to-nearest via magic number
    int   n = __float_as_int(r) - 0x4B400000;
    float f = t - (r - 12582912.0f);           // f in [-0.5, 0.5]
    float p = 0.0013333558f;
    p = fmaf(p, f, 0.0096181291f);
    p = fmaf(p, f, 0.0555041087f);
    p = fmaf(p, f, 0.2402265070f);
    p = fmaf(p, f, 0.6931471806f);
    p = fmaf(p, f, 1.0f);
    return __int_as_float((n + 127) << 23) * p;
}

// ---------------- CSR build ----------------
__global__ void k_zero() {
    int i = blockIdx.x * blockDim.x + threadIdx.x;
    if (i < Nn) { g_deg[i] = 0; g_off[i] = 0; }
}

__global__ void k_hist(const int* __restrict__ ei) {
    int e = blockIdx.x * blockDim.x + threadIdx.x;
    if (e >= EP) return;
    int dst = (e < Ee) ? ei[Ee + e] : (e - Ee);
    atomicAdd(&g_deg[dst], 1);
}

__global__ void k_scan() {
    __shared__ int warp_sums[32];
    __shared__ int s_carry;
    int tid = threadIdx.x, lane = tid & 31, wid = tid >> 5;
    if (tid == 0) s_carry = 0;
    __syncthreads();
    for (int base = 0; base < Nn; base += 1024) {
        int i = base + tid;
        int v = (i < Nn) ? g_deg[i] : 0;
        int incl = v;
        #pragma unroll
        for (int o = 1; o < 32; o <<= 1) {
            int t = __shfl_up_sync(0xffffffffu, incl, o);
            if (lane >= o) incl += t;
        }
        if (lane == 31) warp_sums[wid] = incl;
        __syncthreads();
        if (wid == 0) {
            int ws = warp_sums[lane];
            int wi = ws;
            #pragma unroll
            for (int o = 1; o < 32; o <<= 1) {
                int t = __shfl_up_sync(0xffffffffu, wi, o);
                if (lane >= o) wi += t;
            }
            warp_sums[lane] = wi - ws;   // exclusive warp base
        }
        __syncthreads();
        int excl = incl - v + warp_sums[wid] + s_carry;
        if (i < Nn) g_rowptr[i] = excl;
        __syncthreads();
        if (tid == 1023) s_carry = excl + v;
        __syncthreads();
    }
    if (tid == 0) g_rowptr[Nn] = s_carry;
}

__global__ void k_scatter(const int* __restrict__ ei) {
    int e = blockIdx.x * blockDim.x + threadIdx.x;
    if (e >= EP) return;
    int src, dst;
    if (e < Ee) { src = ei[e]; dst = ei[Ee + e]; }
    else        { src = dst = e - Ee; }
    int pos = g_rowptr[dst] + atomicAdd(&g_off[dst], 1);
    g_ssrc[pos] = src;
    g_seid[pos] = e;
}

// ---------------- GEMM: Y[N, NC] = X[N,128] @ W[128, NC] ----------------
template<int NC>
__global__ void k_gemm(const float* __restrict__ X, const float* __restrict__ W,
                       float* __restrict__ Y) {
    constexpr int CG = NC / 4;        // col groups of 4
    constexpr int RT = 512 / CG;      // rows per tile
    __shared__ float xs[RT][129];     // pad to kill bank conflicts
    int tx = threadIdx.x % CG;
    int ty = threadIdx.x / CG;
    int row0 = blockIdx.x * RT;
    for (int idx = threadIdx.x; idx < RT * 128; idx += 512) {
        int r = idx >> 7, c = idx & 127;
        int gr = row0 + r;
        xs[r][c] = (gr < Nn) ? X[gr * 128 + c] : 0.f;
    }
    __syncthreads();
    float4 acc = make_float4(0.f, 0.f, 0.f, 0.f);
    #pragma unroll 16
    for (int k = 0; k < 128; k++) {
        float xv = xs[ty][k];
        float4 w4 = *reinterpret_cast<const float4*>(W + k * NC + tx * 4);
        acc.x = fmaf(xv, w4.x, acc.x);
        acc.y = fmaf(xv, w4.y, acc.y);
        acc.z = fmaf(xv, w4.z, acc.z);
        acc.w = fmaf(xv, w4.w, acc.w);
    }
    int gr = row0 + ty;
    if (gr < Nn)
        *reinterpret_cast<float4*>(Y + gr * NC + tx * 4) = acc;
}

// ---------------- per-node attention half-logits, 4 heads ----------------
__global__ void k_alpha4(const float* __restrict__ H, const float* __restrict__ as,
                         const float* __restrict__ ad) {
    int w = (blockIdx.x * blockDim.x + threadIdx.x) >> 5;
    int lane = threadIdx.x & 31;
    if (w >= Nn) return;
    float ps[4], pd[4];
    #pragma unroll
    for (int h = 0; h < 4; h++) {
        float hv = H[w * 128 + h * 32 + lane];
        ps[h] = hv * as[h * 32 + lane];
        pd[h] = hv * ad[h * 32 + lane];
    }
    #pragma unroll
    for (int o = 16; o; o >>= 1) {
        #pragma unroll
        for (int h = 0; h < 4; h++) {
            ps[h] += __shfl_xor_sync(0xffffffffu, ps[h], o);
            pd[h] += __shfl_xor_sync(0xffffffffu, pd[h], o);
        }
    }
    if (lane == 0) {
        *reinterpret_cast<float4*>(g_asrc + w * 4) = make_float4(ps[0], ps[1], ps[2], ps[3]);
        *reinterpret_cast<float4*>(g_adst + w * 4) = make_float4(pd[0], pd[1], pd[2], pd[3]);
    }
}

__global__ void k_alpha1(const float* __restrict__ H2, const float* __restrict__ as,
                         const float* __restrict__ ad) {
    int w = (blockIdx.x * blockDim.x + threadIdx.x) >> 5;
    int lane = threadIdx.x & 31;
    if (w >= Nn) return;
    float hv = H2[w * 32 + lane];
    float ps = hv * as[lane];
    float pd = hv * ad[lane];
    #pragma unroll
    for (int o = 16; o; o >>= 1) {
        ps += __shfl_xor_sync(0xffffffffu, ps, o);
        pd += __shfl_xor_sync(0xffffffffu, pd, o);
    }
    if (lane == 0) { g_as2[w] = ps; g_ad2[w] = pd; }
}

// ---------------- edge kernel, 4 heads x 32 ch (one warp per dst node) ----------------
template<bool WRITE_ALPHA>
__global__ void k_edge4(const float* __restrict__ H, const float* __restrict__ bias,
                        float* __restrict__ Xout, float* __restrict__ alpha_out) {
    __shared__ float cache[8][CACHE_MAX][4];   // 16 KB
    int wl = threadIdx.x >> 5;
    int lane = threadIdx.x & 31;
    int w = (blockIdx.x * blockDim.x + threadIdx.x) >> 5;
    if (w >= Nn) return;
    int beg = g_rowptr[w], end = g_rowptr[w + 1];
    int deg = end - beg;
    float4 adv = *reinterpret_cast<const float4*>(g_adst + 4 * w);

    // ---- pass A1: per-head max (no exp) ----
    float m0 = -1e30f, m1 = -1e30f, m2 = -1e30f, m3 = -1e30f;
    for (int e = beg + lane; e < end; e += 32) {
        int src = g_ssrc[e];
        float4 a = *reinterpret_cast<const float4*>(g_asrc + 4 * src);
        m0 = fmaxf(m0, lrelu(a.x + adv.x));
        m1 = fmaxf(m1, lrelu(a.y + adv.y));
        m2 = fmaxf(m2, lrelu(a.z + adv.z));
        m3 = fmaxf(m3, lrelu(a.w + adv.w));
    }
    #pragma unroll
    for (int o = 16; o; o >>= 1) {
        m0 = fmaxf(m0, __shfl_xor_sync(0xffffffffu, m0, o));
        m1 = fmaxf(m1, __shfl_xor_sync(0xffffffffu, m1, o));
        m2 = fmaxf(m2, __shfl_xor_sync(0xffffffffu, m2, o));
        m3 = fmaxf(m3, __shfl_xor_sync(0xffffffffu, m3, o));
    }

    int head = lane >> 3;                       // 8 lanes per head
    float mh  = head == 0 ? m0 : head == 1 ? m1 : head == 2 ? m2 : m3;
    float adh = head == 0 ? adv.x : head == 1 ? adv.y : head == 2 ? adv.z : adv.w;
    bool cached = (deg <= CACHE_MAX);

    // ---- pass A2: exp once per (edge, head), cache + partial sum ----
    float psum = 0.f;
    for (int eo = lane & 7; eo < deg; eo += 8) {
        int src = g_ssrc[beg + eo];
        float l = lrelu(g_asrc[src * 4 + head] + adh);
        float ev = fexp(l - mh);
        if (cached) cache[wl][eo][head] = ev;
        psum += ev;
    }
    #pragma unroll
    for (int o = 1; o < 8; o <<= 1)
        psum += __shfl_xor_sync(0xffffffffu, psum, o);   // per-head (8-lane group) sum
    float inv = 1.f / psum;

    // ---- pass B: weighted aggregate (lane covers 4 channels of its head) ----
    float4 acc = make_float4(0.f, 0.f, 0.f, 0.f);
    const float4* H4 = reinterpret_cast<const float4*>(H);
    for (int eo = 0; eo < deg; eo++) {
        int e = beg + eo;
        int src = g_ssrc[e];
        float ev;
        if (cached) ev = cache[wl][eo][head];
        else {
            float l = lrelu(g_asrc[src * 4 + head] + adh);
            ev = fexp(l - mh);
        }
        float alpha = ev * inv;
        float4 hv = H4[src * 32 + lane];
        acc.x = fmaf(alpha, hv.x, acc.x);
        acc.y = fmaf(alpha, hv.y, acc.y);
        acc.z = fmaf(alpha, hv.z, acc.z);
        acc.w = fmaf(alpha, hv.w, acc.w);
        if (WRITE_ALPHA && (lane & 7) == 0)
            alpha_out[(size_t)g_seid[e] * 4 + head] = alpha;
    }

    // ---- epilogue: + bias, ELU, store ----
    float4 b = *reinterpret_cast<const float4*>(bias + lane * 4);
    acc.x += b.x; acc.y += b.y; acc.z += b.z; acc.w += b.w;
    acc.x = acc.x > 0.f ? acc.x : expm1f(acc.x);
    acc.y = acc.y > 0.f ? acc.y : expm1f(acc.y);
    acc.z = acc.z > 0.f ? acc.z : expm1f(acc.z);
    acc.w = acc.w > 0.f ? acc.w : expm1f(acc.w);
    *reinterpret_cast<float4*>(Xout + w * 128 + lane * 4) = acc;
}

// ---------------- edge kernel, 1 head x 32 ch (final layer) ----------------
__global__ void k_edge1(const float* __restrict__ H2, const float* __restrict__ bias,
                        float* __restrict__ Out) {
    __shared__ float cache[8][CACHE_MAX];      // 4 KB
    int wl = threadIdx.x >> 5;
    int lane = threadIdx.x & 31;
    int w = (blockIdx.x * blockDim.x + threadIdx.x) >> 5;
    if (w >= Nn) return;
    int beg = g_rowptr[w], end = g_rowptr[w + 1];
    int deg = end - beg;
    float adv = g_ad2[w];

    float m = -1e30f;
    for (int e = beg + lane; e < end; e += 32) {
        int src = g_ssrc[e];
        m = fmaxf(m, lrelu(g_as2[src] + adv));
    }
    #pragma unroll
    for (int o = 16; o; o >>= 1) m = fmaxf(m, __shfl_xor_sync(0xffffffffu, m, o));

    bool cached = (deg <= CACHE_MAX);
    float ps = 0.f;
    for (int eo = lane; eo < deg; eo += 32) {
        int src = g_ssrc[beg + eo];
        float ev = fexp(lrelu(g_as2[src] + adv) - m);
        if (cached) cache[wl][eo] = ev;
        ps += ev;
    }
    #pragma unroll
    for (int o = 16; o; o >>= 1) ps += __shfl_xor_sync(0xffffffffu, ps, o);
    float inv = 1.f / ps;

    float acc = 0.f;
    for (int eo = 0; eo < deg; eo++) {
        int src = g_ssrc[beg + eo];
        float ev;
        if (cached) ev = cache[wl][eo];
        else ev = fexp(lrelu(g_as2[src] + adv) - m);
        acc = fmaf(ev * inv, H2[src * 32 + lane], acc);
    }
    Out[w * 32 + lane] = acc + bias[lane];
}

// ---------------- launch ----------------
extern "C" void kernel_launch(void* const* d_in, const int* in_sizes, int n_in,
                              void* d_out, int out_size) {
    const float* x   = (const float*)d_in[0];
    const int*   ei  = (const int*)  d_in[1];
    const float* W0  = (const float*)d_in[2];
    const float* as0 = (const float*)d_in[3];
    const float* ad0 = (const float*)d_in[4];
    const float* b0  = (const float*)d_in[5];
    const float* W1  = (const float*)d_in[6];
    const float* as1 = (const float*)d_in[7];
    const float* ad1 = (const float*)d_in[8];
    const float* b1  = (const float*)d_in[9];
    const float* W2  = (const float*)d_in[10];
    const float* as2 = (const float*)d_in[11];
    const float* ad2 = (const float*)d_in[12];
    const float* b2  = (const float*)d_in[13];

    float* out        = (float*)d_out;
    float* alpha0_out = out;                        // [EP, 4]
    float* final_out  = out + (size_t)EP * 4;       // [Nn, 32]

    float *p_h, *p_x1, *p_h2;
    cudaGetSymbolAddress((void**)&p_h,  g_h);
    cudaGetSymbolAddress((void**)&p_x1, g_x1);
    cudaGetSymbolAddress((void**)&p_h2, g_h2);

    // CSR by destination
    k_zero   <<<(Nn + 255) / 256, 256>>>();
    k_hist   <<<(EP + 255) / 256, 256>>>(ei);
    k_scan   <<<1, 1024>>>();
    k_scatter<<<(EP + 255) / 256, 256>>>(ei);

    // layer 0
    k_gemm<128><<<(Nn + 15) / 16, 512>>>(x, W0, p_h);
    k_alpha4<<<(Nn + 7) / 8, 256>>>(p_h, as0, ad0);
    k_edge4<true><<<(Nn + 7) / 8, 256>>>(p_h, b0, p_x1, alpha0_out);

    // layer 1
    k_gemm<128><<<(Nn + 15) / 16, 512>>>(p_x1, W1, p_h);
    k_alpha4<<<(Nn + 7) / 8, 256>>>(p_h, as1, ad1);
    k_edge4<false><<<(Nn + 7) / 8, 256>>>(p_h, b1, p_x1, nullptr);

    // layer 2
    k_gemm<32><<<(Nn + 63) / 64, 512>>>(p_x1, W2, p_h2);
    k_alpha1<<<(Nn + 7) / 8, 256>>>(p_h2, as2, ad2);
    k_edge1<<<(Nn + 7) / 8, 256>>>(p_h2, b2, final_out);
}

// round 2
// speedup vs baseline: 1.3998x; 1.3998x over previous
#include <cuda_runtime.h>
#include <math.h>
#include <stdint.h>

#define Nn 50000
#define Ee 1600000
#define EP 1650000          // Ee + Nn self loops
#define CACHE_MAX 128       // per-node cached slots (deg ~ Poisson(33); P(deg>128) ~ 0)
#define NB_SCAN 49          // ceil(Nn/1024)

// ---------------- device scratch (static, no allocation) ----------------
__device__ int   g_deg[Nn];
__device__ int   g_off[Nn];
__device__ int   g_rowptr[Nn + 1];
__device__ int2  g_sedge[EP];          // (src, edge_id) packed
__device__ int   g_bsum[64];
__device__ int   g_boff[64];
__device__ float g_h [Nn * 128];
__device__ float g_x1[Nn * 128];
__device__ float g_h2[Nn * 32];
__device__ float g_asrc[Nn * 4];
__device__ float g_adst[Nn * 4];
__device__ float g_as2[Nn];
__device__ float g_ad2[Nn];

// ---------------- helpers ----------------
__device__ __forceinline__ float lrelu(float x) { return x > 0.f ? x : 0.2f * x; }

// FMA-only exp (no MUFU). Valid for x <= ~30; clamps below -80 (result ~0).
__device__ __forceinline__ float fexp(float x) {
    x = fmaxf(x, -80.0f);
    float t = x * 1.4426950408889634f;
    float r = t + 12582912.0f;                 // round-to-nearest via magic number
    int   n = __float_as_int(r) - 0x4B400000;
    float f = t - (r - 12582912.0f);           // f in [-0.5, 0.5]
    float p = 0.0013333558f;
    p = fmaf(p, f, 0.0096181291f);
    p = fmaf(p, f, 0.0555041087f);
    p = fmaf(p, f, 0.2402265070f);
    p = fmaf(p, f, 0.6931471806f);
    p = fmaf(p, f, 1.0f);
    return __int_as_float((n + 127) << 23) * p;
}

__device__ __forceinline__ void ffma2(unsigned long long& d, unsigned long long a,
                                      unsigned long long b) {
    asm("fma.rn.f32x2 %0, %1, %2, %0;" : "+l"(d) : "l"(a), "l"(b));
}
__device__ __forceinline__ unsigned long long pack2(float v) {
    unsigned long long p;
    asm("mov.b64 %0, {%1, %1};" : "=l"(p) : "r"(__float_as_uint(v)));
    return p;
}

// ---------------- CSR build ----------------
__global__ void k_zero() {
    int i = blockIdx.x * blockDim.x + threadIdx.x;
    if (i < Nn) g_deg[i] = 0;
}

__global__ void k_hist(const int* __restrict__ ei) {
    int e = blockIdx.x * blockDim.x + threadIdx.x;
    if (e >= EP) return;
    int dst = (e < Ee) ? ei[Ee + e] : (e - Ee);
    atomicAdd(&g_deg[dst], 1);            // return unused -> RED
}

// phase 1: per-1024-block exclusive scan, block sums to g_bsum
__global__ void k_scan1() {
    __shared__ int warp_sums[32];
    int tid = threadIdx.x, lane = tid & 31, wid = tid >> 5;
    int i = blockIdx.x * 1024 + tid;
    int v = (i < Nn) ? g_deg[i] : 0;
    int incl = v;
    #pragma unroll
    for (int o = 1; o < 32; o <<= 1) {
        int t = __shfl_up_sync(0xffffffffu, incl, o);
        if (lane >= o) incl += t;
    }
    if (lane == 31) warp_sums[wid] = incl;
    __syncthreads();
    if (wid == 0) {
        int ws = warp_sums[lane];
        int wi = ws;
        #pragma unroll
        for (int o = 1; o < 32; o <<= 1) {
            int t = __shfl_up_sync(0xffffffffu, wi, o);
            if (lane >= o) wi += t;
        }
        warp_sums[lane] = wi - ws;
    }
    __syncthreads();
    int excl = incl - v + warp_sums[wid];
    if (i < Nn) g_rowptr[i] = excl;
    if (tid == 1023) g_bsum[blockIdx.x] = excl + v;
}

// phase 2: single warp scans NB_SCAN block sums -> exclusive g_boff
__global__ void k_scan2() {
    int lane = threadIdx.x;
    int carry = 0;
    for (int base = 0; base < NB_SCAN; base += 32) {
        int i = base + lane;
        int v = (i < NB_SCAN) ? g_bsum[i] : 0;
        int incl = v;
        #pragma unroll
        for (int o = 1; o < 32; o <<= 1) {
            int t = __shfl_up_sync(0xffffffffu, incl, o);
            if (lane >= o) incl += t;
        }
        if (i < NB_SCAN) g_boff[i] = incl - v + carry;
        carry += __shfl_sync(0xffffffffu, incl, 31);
    }
}

// phase 3: add block offsets; zero g_off; set rowptr[Nn]
__global__ void k_scan3() {
    int i = blockIdx.x * blockDim.x + threadIdx.x;
    if (i < Nn) {
        g_rowptr[i] += g_boff[i >> 10];
        g_off[i] = 0;
    }
    if (i == 0) g_rowptr[Nn] = EP;
}

__global__ void k_scatter(const int* __restrict__ ei) {
    int e = blockIdx.x * blockDim.x + threadIdx.x;
    if (e >= EP) return;
    int src, dst;
    if (e < Ee) { src = ei[e]; dst = ei[Ee + e]; }
    else        { src = dst = e - Ee; }
    int pos = g_rowptr[dst] + atomicAdd(&g_off[dst], 1);
    g_sedge[pos] = make_int2(src, e);
}

// ---------------- GEMM 128x128 with packed f32x2 FMA ----------------
// Y[N,128] = X[N,128] @ W[128,128]. Block: 256 threads, 64-row tile.
// Thread: 4 rows x 8 cols (4 packed col-pairs) = 16 FFMA2 per k.
__global__ void k_gemm128(const float* __restrict__ X, const float* __restrict__ W,
                          float* __restrict__ Y) {
    __shared__ float xs[64][128];
    int ct = threadIdx.x & 15, rt = threadIdx.x >> 4;
    int row0 = blockIdx.x * 64;
    for (int idx = threadIdx.x; idx < 64 * 128; idx += 256) {
        int r = idx >> 7, c = idx & 127;
        int gr = row0 + r;
        xs[r][c] = (gr < Nn) ? X[gr * 128 + c] : 0.f;
    }
    __syncthreads();
    int r0 = rt * 4, c0 = ct * 8;
    unsigned long long acc[4][4];
    #pragma unroll
    for (int r = 0; r < 4; r++)
        #pragma unroll
        for (int c = 0; c < 4; c++) acc[r][c] = 0ull;

    const float* Wc = W + c0;
    #pragma unroll 2
    for (int k = 0; k < 128; k++) {
        ulonglong2 wa = *reinterpret_cast<const ulonglong2*>(Wc + (size_t)k * 128);
        ulonglong2 wb = *reinterpret_cast<const ulonglong2*>(Wc + (size_t)k * 128 + 4);
        #pragma unroll
        for (int r = 0; r < 4; r++) {
            unsigned long long xp = pack2(xs[r0 + r][k]);
            ffma2(acc[r][0], xp, wa.x);
            ffma2(acc[r][1], xp, wa.y);
            ffma2(acc[r][2], xp, wb.x);
            ffma2(acc[r][3], xp, wb.y);
        }
    }
    #pragma unroll
    for (int r = 0; r < 4; r++) {
        int gr = row0 + r0 + r;
        if (gr >= Nn) continue;
        float o[8];
        #pragma unroll
        for (int c = 0; c < 4; c++)
            asm("mov.b64 {%0, %1}, %2;" : "=f"(o[2 * c]), "=f"(o[2 * c + 1]) : "l"(acc[r][c]));
        *reinterpret_cast<float4*>(Y + (size_t)gr * 128 + c0) =
            make_float4(o[0], o[1], o[2], o[3]);
        *reinterpret_cast<float4*>(Y + (size_t)gr * 128 + c0 + 4) =
            make_float4(o[4], o[5], o[6], o[7]);
    }
}

// ---------------- GEMM: Y[N, 32] = X[N,128] @ W[128, 32] ----------------
__global__ void k_gemm32(const float* __restrict__ X, const float* __restrict__ W,
                         float* __restrict__ Y) {
    constexpr int CG = 8;             // col groups of 4
    constexpr int RT = 64;            // rows per tile
    __shared__ float xs[RT][129];
    int tx = threadIdx.x % CG;
    int ty = threadIdx.x / CG;
    int row0 = blockIdx.x * RT;
    for (int idx = threadIdx.x; idx < RT * 128; idx += 512) {
        int r = idx >> 7, c = idx & 127;
        int gr = row0 + r;
        xs[r][c] = (gr < Nn) ? X[gr * 128 + c] : 0.f;
    }
    __syncthreads();
    float4 acc = make_float4(0.f, 0.f, 0.f, 0.f);
    #pragma unroll 16
    for (int k = 0; k < 128; k++) {
        float xv = xs[ty][k];
        float4 w4 = *reinterpret_cast<const float4*>(W + k * 32 + tx * 4);
        acc.x = fmaf(xv, w4.x, acc.x);
        acc.y = fmaf(xv, w4.y, acc.y);
        acc.z = fmaf(xv, w4.z, acc.z);
        acc.w = fmaf(xv, w4.w, acc.w);
    }
    int gr = row0 + ty;
    if (gr < Nn)
        *reinterpret_cast<float4*>(Y + gr * 32 + tx * 4) = acc;
}

// ---------------- per-node attention half-logits ----------------
__global__ void k_alpha4(const float* __restrict__ H, const float* __restrict__ as,
                         const float* __restrict__ ad) {
    int w = (blockIdx.x * blockDim.x + threadIdx.x) >> 5;
    int lane = threadIdx.x & 31;
    if (w >= Nn) return;
    float ps[4], pd[4];
    #pragma unroll
    for (int h = 0; h < 4; h++) {
        float hv = H[w * 128 + h * 32 + lane];
        ps[h] = hv * as[h * 32 + lane];
        pd[h] = hv * ad[h * 32 + lane];
    }
    #pragma unroll
    for (int o = 16; o; o >>= 1) {
        #pragma unroll
        for (int h = 0; h < 4; h++) {
            ps[h] += __shfl_xor_sync(0xffffffffu, ps[h], o);
            pd[h] += __shfl_xor_sync(0xffffffffu, pd[h], o);
        }
    }
    if (lane == 0) {
        *reinterpret_cast<float4*>(g_asrc + w * 4) = make_float4(ps[0], ps[1], ps[2], ps[3]);
        *reinterpret_cast<float4*>(g_adst + w * 4) = make_float4(pd[0], pd[1], pd[2], pd[3]);
    }
}

__global__ void k_alpha1(const float* __restrict__ H2, const float* __restrict__ as,
                         const float* __restrict__ ad) {
    int w = (blockIdx.x * blockDim.x + threadIdx.x) >> 5;
    int lane = threadIdx.x & 31;
    if (w >= Nn) return;
    float hv = H2[w * 32 + lane];
    float ps = hv * as[lane];
    float pd = hv * ad[lane];
    #pragma unroll
    for (int o = 16; o; o >>= 1) {
        ps += __shfl_xor_sync(0xffffffffu, ps, o);
        pd += __shfl_xor_sync(0xffffffffu, pd, o);
    }
    if (lane == 0) { g_as2[w] = ps; g_ad2[w] = pd; }
}

// ---------------- edge kernel, 4 heads x 32 ch (one warp per dst) ----------------
template<bool WRITE_ALPHA>
__global__ void k_edge4(const float* __restrict__ H, const float* __restrict__ bias,
                        float* __restrict__ Xout, float* __restrict__ alpha_out) {
    __shared__ float4 cache4[8][CACHE_MAX];   // 16 KB (alpha per edge, 4 heads)
    __shared__ int    ssm[8][CACHE_MAX];      //  4 KB (src per edge)
    int wl = threadIdx.x >> 5;
    int lane = threadIdx.x & 31;
    int w = (blockIdx.x * blockDim.x + threadIdx.x) >> 5;
    if (w >= Nn) return;
    int beg = g_rowptr[w];
    int deg = g_rowptr[w + 1] - beg;
    float4 adv = *reinterpret_cast<const float4*>(g_adst + 4 * w);
    int head = lane >> 3;
    float adh = head == 0 ? adv.x : head == 1 ? adv.y : head == 2 ? adv.z : adv.w;
    float* cf = reinterpret_cast<float*>(cache4[wl]);
    const float4* H4 = reinterpret_cast<const float4*>(H);
    float4 acc = make_float4(0.f, 0.f, 0.f, 0.f);

    if (deg <= CACHE_MAX) {
        // stage src indices (coalesced)
        for (int eo = lane; eo < deg; eo += 32)
            ssm[wl][eo] = g_sedge[beg + eo].x;
        __syncwarp();
        // exp once per (edge, head); softmax shift-invariant -> no max pass
        float psum = 0.f;
        for (int eo = lane & 7; eo < deg; eo += 8) {
            int src = ssm[wl][eo];
            float ev = fexp(lrelu(__ldg(g_asrc + src * 4 + head) + adh));
            cf[eo * 4 + head] = ev;
            psum += ev;
        }
        psum += __shfl_xor_sync(0xffffffffu, psum, 1);
        psum += __shfl_xor_sync(0xffffffffu, psum, 2);
        psum += __shfl_xor_sync(0xffffffffu, psum, 4);
        float inv = 1.f / psum;
        for (int eo = lane & 7; eo < deg; eo += 8)
            cf[eo * 4 + head] *= inv;                 // cache now holds alpha
        __syncwarp();
        if (WRITE_ALPHA) {
            for (int eo = lane; eo < deg; eo += 32) {
                int eid = g_sedge[beg + eo].y;
                *reinterpret_cast<float4*>(alpha_out + (size_t)eid * 4) = cache4[wl][eo];
            }
        }
        // pass B: 4-way unrolled gather-accumulate (4 LDGs in flight)
        int eo = 0;
        for (; eo + 4 <= deg; eo += 4) {
            int s0 = ssm[wl][eo], s1 = ssm[wl][eo + 1];
            int s2 = ssm[wl][eo + 2], s3 = ssm[wl][eo + 3];
            float a0 = cf[eo * 4 + head],       a1 = cf[(eo + 1) * 4 + head];
            float a2 = cf[(eo + 2) * 4 + head], a3 = cf[(eo + 3) * 4 + head];
            float4 h0 = H4[s0 * 32 + lane];
            float4 h1 = H4[s1 * 32 + lane];
            float4 h2 = H4[s2 * 32 + lane];
            float4 h3 = H4[s3 * 32 + lane];
            acc.x = fmaf(a0, h0.x, acc.x); acc.y = fmaf(a0, h0.y, acc.y);
            acc.z = fmaf(a0, h0.z, acc.z); acc.w = fmaf(a0, h0.w, acc.w);
            acc.x = fmaf(a1, h1.x, acc.x); acc.y = fmaf(a1, h1.y, acc.y);
            acc.z = fmaf(a1, h1.z, acc.z); acc.w = fmaf(a1, h1.w, acc.w);
            acc.x = fmaf(a2, h2.x, acc.x); acc.y = fmaf(a2, h2.y, acc.y);
            acc.z = fmaf(a2, h2.z, acc.z); acc.w = fmaf(a2, h2.w, acc.w);
            acc.x = fmaf(a3, h3.x, acc.x); acc.y = fmaf(a3, h3.y, acc.y);
            acc.z = fmaf(a3, h3.z, acc.z); acc.w = fmaf(a3, h3.w, acc.w);
        }
        for (; eo < deg; eo++) {
            int s = ssm[wl][eo];
            float a = cf[eo * 4 + head];
            float4 hv = H4[s * 32 + lane];
            acc.x = fmaf(a, hv.x, acc.x); acc.y = fmaf(a, hv.y, acc.y);
            acc.z = fmaf(a, hv.z, acc.z); acc.w = fmaf(a, hv.w, acc.w);
        }
    } else {
        // slow path (deg > CACHE_MAX): recompute exp in pass B
        float psum = 0.f;
        for (int eo = lane & 7; eo < deg; eo += 8) {
            int src = g_sedge[beg + eo].x;
            psum += fexp(lrelu(g_asrc[src * 4 + head] + adh));
        }
        psum += __shfl_xor_sync(0xffffffffu, psum, 1);
        psum += __shfl_xor_sync(0xffffffffu, psum, 2);
        psum += __shfl_xor_sync(0xffffffffu, psum, 4);
        float inv = 1.f / psum;
        for (int eo = 0; eo < deg; eo++) {
            int2 se = g_sedge[beg + eo];
            float ev = fexp(lrelu(g_asrc[se.x * 4 + head] + adh));
            float alpha = ev * inv;
            float4 hv = H4[se.x * 32 + lane];
            acc.x = fmaf(alpha, hv.x, acc.x); acc.y = fmaf(alpha, hv.y, acc.y);
            acc.z = fmaf(alpha, hv.z, acc.z); acc.w = fmaf(alpha, hv.w, acc.w);
            if (WRITE_ALPHA && (lane & 7) == 0)
                alpha_out[(size_t)se.y * 4 + head] = alpha;
        }
    }

    float4 b = *reinterpret_cast<const float4*>(bias + lane * 4);
    acc.x += b.x; acc.y += b.y; acc.z += b.z; acc.w += b.w;
    acc.x = acc.x > 0.f ? acc.x : expm1f(acc.x);
    acc.y = acc.y > 0.f ? acc.y : expm1f(acc.y);
    acc.z = acc.z > 0.f ? acc.z : expm1f(acc.z);
    acc.w = acc.w > 0.f ? acc.w : expm1f(acc.w);
    *reinterpret_cast<float4*>(Xout + w * 128 + lane * 4) = acc;
}

// ---------------- edge kernel, 1 head x 32 ch (final layer) ----------------
__global__ void k_edge1(const float* __restrict__ H2, const float* __restrict__ bias,
                        float* __restrict__ Out) {
    __shared__ float cache[8][CACHE_MAX];
    __shared__ int   ssm[8][CACHE_MAX];
    int wl = threadIdx.x >> 5;
    int lane = threadIdx.x & 31;
    int w = (blockIdx.x * blockDim.x + threadIdx.x) >> 5;
    if (w >= Nn) return;
    int beg = g_rowptr[w];
    int deg = g_rowptr[w + 1] - beg;
    float adv = g_ad2[w];
    float acc = 0.f;

    if (deg <= CACHE_MAX) {
        float psum = 0.f;
        for (int eo = lane; eo < deg; eo += 32) {
            int src = g_sedge[beg + eo].x;
            ssm[wl][eo] = src;
            float ev = fexp(lrelu(__ldg(g_as2 + src) + adv));
            cache[wl][eo] = ev;
            psum += ev;
        }
        #pragma unroll
        for (int o = 16; o; o >>= 1) psum += __shfl_xor_sync(0xffffffffu, psum, o);
        float inv = 1.f / psum;
        for (int eo = lane; eo < deg; eo += 32) cache[wl][eo] *= inv;
        __syncwarp();
        int eo = 0;
        for (; eo + 4 <= deg; eo += 4) {
            int s0 = ssm[wl][eo], s1 = ssm[wl][eo + 1];
            int s2 = ssm[wl][eo + 2], s3 = ssm[wl][eo + 3];
            float a0 = cache[wl][eo],     a1 = cache[wl][eo + 1];
            float a2 = cache[wl][eo + 2], a3 = cache[wl][eo + 3];
            float h0 = H2[s0 * 32 + lane];
            float h1 = H2[s1 * 32 + lane];
            float h2 = H2[s2 * 32 + lane];
            float h3 = H2[s3 * 32 + lane];
            acc = fmaf(a0, h0, acc);
            acc = fmaf(a1, h1, acc);
            acc = fmaf(a2, h2, acc);
            acc = fmaf(a3, h3, acc);
        }
        for (; eo < deg; eo++)
            acc = fmaf(cache[wl][eo], H2[ssm[wl][eo] * 32 + lane], acc);
    } else {
        float psum = 0.f;
        for (int eo = lane; eo < deg; eo += 32) {
            int src = g_sedge[beg + eo].x;
            psum += fexp(lrelu(g_as2[src] + adv));
        }
        #pragma unroll
        for (int o = 16; o; o >>= 1) psum += __shfl_xor_sync(0xffffffffu, psum, o);
        float inv = 1.f / psum;
        for (int eo = 0; eo < deg; eo++) {
            int src = g_sedge[beg + eo].x;
            float ev = fexp(lrelu(g_as2[src] + adv));
            acc = fmaf(ev * inv, H2[src * 32 + lane], acc);
        }
    }
    Out[w * 32 + lane] = acc + bias[lane];
}

// ---------------- launch ----------------
extern "C" void kernel_launch(void* const* d_in, const int* in_sizes, int n_in,
                              void* d_out, int out_size) {
    const float* x   = (const float*)d_in[0];
    const int*   ei  = (const int*)  d_in[1];
    const float* W0  = (const float*)d_in[2];
    const float* as0 = (const float*)d_in[3];
    const float* ad0 = (const float*)d_in[4];
    const float* b0  = (const float*)d_in[5];
    const float* W1  = (const float*)d_in[6];
    const float* as1 = (const float*)d_in[7];
    const float* ad1 = (const float*)d_in[8];
    const float* b1  = (const float*)d_in[9];
    const float* W2  = (const float*)d_in[10];
    const float* as2 = (const float*)d_in[11];
    const float* ad2 = (const float*)d_in[12];
    const float* b2  = (const float*)d_in[13];

    float* out        = (float*)d_out;
    float* alpha0_out = out;                        // [EP, 4]
    float* final_out  = out + (size_t)EP * 4;       // [Nn, 32]

    float *p_h, *p_x1, *p_h2;
    cudaGetSymbolAddress((void**)&p_h,  g_h);
    cudaGetSymbolAddress((void**)&p_x1, g_x1);
    cudaGetSymbolAddress((void**)&p_h2, g_h2);

    // CSR by destination
    k_zero   <<<(Nn + 255) / 256, 256>>>();
    k_hist   <<<(EP + 255) / 256, 256>>>(ei);
    k_scan1  <<<NB_SCAN, 1024>>>();
    k_scan2  <<<1, 32>>>();
    k_scan3  <<<(Nn + 255) / 256, 256>>>();
    k_scatter<<<(EP + 255) / 256, 256>>>(ei);

    // layer 0
    k_gemm128<<<(Nn + 63) / 64, 256>>>(x, W0, p_h);
    k_alpha4<<<(Nn + 7) / 8, 256>>>(p_h, as0, ad0);
    k_edge4<true><<<(Nn + 7) / 8, 256>>>(p_h, b0, p_x1, alpha0_out);

    // layer 1
    k_gemm128<<<(Nn + 63) / 64, 256>>>(p_x1, W1, p_h);
    k_alpha4<<<(Nn + 7) / 8, 256>>>(p_h, as1, ad1);
    k_edge4<false><<<(Nn + 7) / 8, 256>>>(p_h, b1, p_x1, nullptr);

    // layer 2
    k_gemm32<<<(Nn + 63) / 64, 512>>>(p_x1, W2, p_h2);
    k_alpha1<<<(Nn + 7) / 8, 256>>>(p_h2, as2, ad2);
    k_edge1<<<(Nn + 7) / 8, 256>>>(p_h2, b2, final_out);
}

// round 3
// speedup vs baseline: 1.5013x; 1.0725x over previous
#include <cuda_runtime.h>
#include <math.h>
#include <stdint.h>

#define Nn 50000
#define Ee 1600000
#define EP 1650000          // Ee + Nn self loops
#define CACHE_MAX 128       // per-node cached slots (deg ~ Poisson(33); P(deg>128) ~ 0)
#define NB_SCAN 49          // ceil(Nn/1024)

// ---------------- device scratch (static, no allocation) ----------------
__device__ int   g_deg[Nn];
__device__ int   g_off[Nn];
__device__ int   g_rowptr[Nn + 1];
__device__ int2  g_sedge[EP];          // (src, edge_id) packed
__device__ int   g_flag[64];           // lookback flags: (aggregate<<1)|1
__device__ float g_h [Nn * 128];
__device__ float g_x1[Nn * 128];
__device__ float g_h2[Nn * 32];
__device__ float g_asrc[Nn * 4];
__device__ float g_adst[Nn * 4];
__device__ float g_as2[Nn];
__device__ float g_ad2[Nn];

// ---------------- helpers ----------------
__device__ __forceinline__ float lrelu(float x) { return x > 0.f ? x : 0.2f * x; }

// FMA-only exp (no MUFU). Valid for x <= ~30; clamps below -80 (result ~0).
__device__ __forceinline__ float fexp(float x) {
    x = fmaxf(x, -80.0f);
    float t = x * 1.4426950408889634f;
    float r = t + 12582912.0f;                 // round-to-nearest via magic number
    int   n = __float_as_int(r) - 0x4B400000;
    float f = t - (r - 12582912.0f);           // f in [-0.5, 0.5]
    float p = 0.0013333558f;
    p = fmaf(p, f, 0.0096181291f);
    p = fmaf(p, f, 0.0555041087f);
    p = fmaf(p, f, 0.2402265070f);
    p = fmaf(p, f, 0.6931471806f);
    p = fmaf(p, f, 1.0f);
    return __int_as_float((n + 127) << 23) * p;
}

__device__ __forceinline__ void ffma2(unsigned long long& d, unsigned long long a,
                                      unsigned long long b) {
    asm("fma.rn.f32x2 %0, %1, %2, %0;" : "+l"(d) : "l"(a), "l"(b));
}
__device__ __forceinline__ unsigned long long pack2(float v) {
    unsigned long long p;
    asm("mov.b64 %0, {%1, %1};" : "=l"(p) : "r"(__float_as_uint(v)));
    return p;
}

// ---------------- CSR build ----------------
__global__ void k_zero() {
    int i = blockIdx.x * blockDim.x + threadIdx.x;
    if (i < Nn) g_deg[i] = 0;
    if (i < 64) g_flag[i] = 0;
}

__global__ void k_hist(const int* __restrict__ ei) {
    int e = blockIdx.x * blockDim.x + threadIdx.x;
    if (e >= EP) return;
    int dst = (e < Ee) ? ei[Ee + e] : (e - Ee);
    atomicAdd(&g_deg[dst], 1);
}

// single-pass exclusive scan with decoupled lookback (49 blocks, all resident)
__global__ void k_scan() {
    __shared__ int warp_sums[32];
    __shared__ int s_prev;
    int tid = threadIdx.x, lane = tid & 31, wid = tid >> 5;
    int b = blockIdx.x;
    int i = b * 1024 + tid;
    int v = (i < Nn) ? g_deg[i] : 0;
    int incl = v;
    #pragma unroll
    for (int o = 1; o < 32; o <<= 1) {
        int t = __shfl_up_sync(0xffffffffu, incl, o);
        if (lane >= o) incl += t;
    }
    if (lane == 31) warp_sums[wid] = incl;
    __syncthreads();
    if (wid == 0) {
        int ws = warp_sums[lane];
        int wi = ws;
        #pragma unroll
        for (int o = 1; o < 32; o <<= 1) {
            int t = __shfl_up_sync(0xffffffffu, wi, o);
            if (lane >= o) wi += t;
        }
        warp_sums[lane] = wi - ws;   // exclusive warp base
    }
    __syncthreads();
    int excl = incl - v + warp_sums[wid];
    // publish block aggregate ASAP (value<<1 | 1); aggregates < 2^22 so no overflow
    if (tid == 1023) atomicExch(&g_flag[b], ((excl + v) << 1) | 1);
    // lookback: warp 0 sums aggregates of all previous blocks
    if (wid == 0) {
        int sum = 0;
        for (int base = 0; base < b; base += 32) {
            int j = base + lane;
            int f = 0;
            if (j < b) {
                do { f = atomicOr(&g_flag[j], 0); } while (!(f & 1));
                sum += (f >> 1);
            }
        }
        #pragma unroll
        for (int o = 16; o; o >>= 1) sum += __shfl_xor_sync(0xffffffffu, sum, o);
        if (lane == 0) s_prev = sum;
    }
    __syncthreads();
    if (i < Nn) {
        g_rowptr[i] = excl + s_prev;
        g_off[i] = 0;
    }
    if (b == 0 && tid == 0) g_rowptr[Nn] = EP;
}

__global__ void k_scatter(const int* __restrict__ ei) {
    int e = blockIdx.x * blockDim.x + threadIdx.x;
    if (e >= EP) return;
    int src, dst;
    if (e < Ee) { src = ei[e]; dst = ei[Ee + e]; }
    else        { src = dst = e - Ee; }
    int pos = g_rowptr[dst] + atomicAdd(&g_off[dst], 1);
    g_sedge[pos] = make_int2(src, e);
}

// ---------------- GEMM 128x128, W staged in SMEM, fused alpha epilogue ----------
// Y[N,128] = X[N,128] @ W[128,128]; also writes g_asrc/g_adst (per-head dots).
// Block: 256 threads, 64-row tile. Thread: 4 rows x 8 cols (4 packed pairs).
// Dynamic SMEM: ws[128*128] (64KB) + xs[64][129] (33KB).
__global__ void k_gemm128(const float* __restrict__ X, const float* __restrict__ W,
                          float* __restrict__ Y,
                          const float* __restrict__ as, const float* __restrict__ ad) {
    extern __shared__ float dyn[];
    float* ws = dyn;                               // [128][128]
    float (*xs)[129] = reinterpret_cast<float (*)[129]>(dyn + 128 * 128);
    int ct = threadIdx.x & 15, rt = threadIdx.x >> 4;
    int lane = threadIdx.x & 31;
    int row0 = blockIdx.x * 64;
    // stage W (64KB) via float4
    for (int idx = threadIdx.x; idx < 128 * 32; idx += 256)
        reinterpret_cast<float4*>(ws)[idx] = reinterpret_cast<const float4*>(W)[idx];
    // stage X tile
    for (int idx = threadIdx.x; idx < 64 * 128; idx += 256) {
        int r = idx >> 7, c = idx & 127;
        int gr = row0 + r;
        xs[r][c] = (gr < Nn) ? X[gr * 128 + c] : 0.f;
    }
    __syncthreads();
    int r0 = rt * 4, c0 = ct * 8;
    unsigned long long acc[4][4];
    #pragma unroll
    for (int r = 0; r < 4; r++)
        #pragma unroll
        for (int c = 0; c < 4; c++) acc[r][c] = 0ull;

    const float* wsc = ws + c0;
    #pragma unroll 2
    for (int k = 0; k < 128; k++) {
        ulonglong2 wa = *reinterpret_cast<const ulonglong2*>(wsc + k * 128);
        ulonglong2 wb = *reinterpret_cast<const ulonglong2*>(wsc + k * 128 + 4);
        #pragma unroll
        for (int r = 0; r < 4; r++) {
            unsigned long long xp = pack2(xs[r0 + r][k]);
            ffma2(acc[r][0], xp, wa.x);
            ffma2(acc[r][1], xp, wa.y);
            ffma2(acc[r][2], xp, wb.x);
            ffma2(acc[r][3], xp, wb.y);
        }
    }
    // per-thread as/ad slice (8 cols, all within one head)
    float asv[8], adv[8];
    #pragma unroll
    for (int c = 0; c < 8; c++) { asv[c] = as[c0 + c]; adv[c] = ad[c0 + c]; }
    int head = ct >> 2;

    #pragma unroll
    for (int r = 0; r < 4; r++) {
        int gr = row0 + r0 + r;
        float o[8];
        #pragma unroll
        for (int c = 0; c < 4; c++)
            asm("mov.b64 {%0, %1}, %2;" : "=f"(o[2 * c]), "=f"(o[2 * c + 1]) : "l"(acc[r][c]));
        if (gr < Nn) {
            *reinterpret_cast<float4*>(Y + (size_t)gr * 128 + c0) =
                make_float4(o[0], o[1], o[2], o[3]);
            *reinterpret_cast<float4*>(Y + (size_t)gr * 128 + c0 + 4) =
                make_float4(o[4], o[5], o[6], o[7]);
        }
        // fused alpha: per-head dot over 32 cols = 4 lanes x 8 cols
        float psA = 0.f, psD = 0.f;
        #pragma unroll
        for (int c = 0; c < 8; c++) {
            psA = fmaf(o[c], asv[c], psA);
            psD = fmaf(o[c], adv[c], psD);
        }
        psA += __shfl_xor_sync(0xffffffffu, psA, 1);
        psA += __shfl_xor_sync(0xffffffffu, psA, 2);
        psD += __shfl_xor_sync(0xffffffffu, psD, 1);
        psD += __shfl_xor_sync(0xffffffffu, psD, 2);
        if ((lane & 3) == 0 && gr < Nn) {
            g_asrc[gr * 4 + head] = psA;
            g_adst[gr * 4 + head] = psD;
        }
    }
}

// ---------------- GEMM: Y[N,32] = X[N,128] @ W[128,32], fused alpha1 ----------
__global__ void k_gemm32(const float* __restrict__ X, const float* __restrict__ W,
                         float* __restrict__ Y,
                         const float* __restrict__ as, const float* __restrict__ ad) {
    constexpr int CG = 8;             // col groups of 4
    constexpr int RT = 64;            // rows per tile
    __shared__ float xs[RT][129];
    __shared__ float wsm[128 * 32];
    int tx = threadIdx.x % CG;
    int ty = threadIdx.x / CG;
    int lane = threadIdx.x & 31;
    int row0 = blockIdx.x * RT;
    for (int idx = threadIdx.x; idx < 128 * 8; idx += 512)
        reinterpret_cast<float4*>(wsm)[idx] = reinterpret_cast<const float4*>(W)[idx];
    for (int idx = threadIdx.x; idx < RT * 128; idx += 512) {
        int r = idx >> 7, c = idx & 127;
        int gr = row0 + r;
        xs[r][c] = (gr < Nn) ? X[gr * 128 + c] : 0.f;
    }
    __syncthreads();
    float4 acc = make_float4(0.f, 0.f, 0.f, 0.f);
    #pragma unroll 16
    for (int k = 0; k < 128; k++) {
        float xv = xs[ty][k];
        float4 w4 = *reinterpret_cast<const float4*>(wsm + k * 32 + tx * 4);
        acc.x = fmaf(xv, w4.x, acc.x);
        acc.y = fmaf(xv, w4.y, acc.y);
        acc.z = fmaf(xv, w4.z, acc.z);
        acc.w = fmaf(xv, w4.w, acc.w);
    }
    int gr = row0 + ty;
    if (gr < Nn)
        *reinterpret_cast<float4*>(Y + gr * 32 + tx * 4) = acc;
    // fused alpha1: dot over 32 cols = 8 lanes x 4 cols
    float4 a4 = *reinterpret_cast<const float4*>(as + tx * 4);
    float4 d4 = *reinterpret_cast<const float4*>(ad + tx * 4);
    float psA = acc.x * a4.x + acc.y * a4.y + acc.z * a4.z + acc.w * a4.w;
    float psD = acc.x * d4.x + acc.y * d4.y + acc.z * d4.z + acc.w * d4.w;
    #pragma unroll
    for (int o = 4; o; o >>= 1) {
        psA += __shfl_xor_sync(0xffffffffu, psA, o);
        psD += __shfl_xor_sync(0xffffffffu, psD, o);
    }
    if ((lane & 7) == 0 && gr < Nn) { g_as2[gr] = psA; g_ad2[gr] = psD; }
}

// ---------------- edge kernel, 4 heads x 32 ch (one warp per dst) ----------------
template<bool WRITE_ALPHA>
__global__ void k_edge4(const float* __restrict__ H, const float* __restrict__ bias,
                        float* __restrict__ Xout, float* __restrict__ alpha_out) {
    __shared__ float4 cache4[8][CACHE_MAX];   // 16 KB (alpha per edge, 4 heads)
    __shared__ int    ssm[8][CACHE_MAX];      //  4 KB (src per edge)
    int wl = threadIdx.x >> 5;
    int lane = threadIdx.x & 31;
    int w = (blockIdx.x * blockDim.x + threadIdx.x) >> 5;
    if (w >= Nn) return;
    int beg = g_rowptr[w];
    int deg = g_rowptr[w + 1] - beg;
    float4 adv = *reinterpret_cast<const float4*>(g_adst + 4 * w);
    int head = lane >> 3;
    float adh = head == 0 ? adv.x : head == 1 ? adv.y : head == 2 ? adv.z : adv.w;
    float* cf = reinterpret_cast<float*>(cache4[wl]);
    const float4* H4 = reinterpret_cast<const float4*>(H);
    float4 acc = make_float4(0.f, 0.f, 0.f, 0.f);

    if (deg <= CACHE_MAX) {
        for (int eo = lane; eo < deg; eo += 32)
            ssm[wl][eo] = g_sedge[beg + eo].x;
        __syncwarp();
        float psum = 0.f;
        for (int eo = lane & 7; eo < deg; eo += 8) {
            int src = ssm[wl][eo];
            float ev = fexp(lrelu(__ldg(g_asrc + src * 4 + head) + adh));
            cf[eo * 4 + head] = ev;
            psum += ev;
        }
        psum += __shfl_xor_sync(0xffffffffu, psum, 1);
        psum += __shfl_xor_sync(0xffffffffu, psum, 2);
        psum += __shfl_xor_sync(0xffffffffu, psum, 4);
        float inv = 1.f / psum;
        for (int eo = lane & 7; eo < deg; eo += 8)
            cf[eo * 4 + head] *= inv;                 // cache now holds alpha
        __syncwarp();
        if (WRITE_ALPHA) {
            for (int eo = lane; eo < deg; eo += 32) {
                int eid = g_sedge[beg + eo].y;
                *reinterpret_cast<float4*>(alpha_out + (size_t)eid * 4) = cache4[wl][eo];
            }
        }
        int eo = 0;
        for (; eo + 4 <= deg; eo += 4) {
            int s0 = ssm[wl][eo], s1 = ssm[wl][eo + 1];
            int s2 = ssm[wl][eo + 2], s3 = ssm[wl][eo + 3];
            float a0 = cf[eo * 4 + head],       a1 = cf[(eo + 1) * 4 + head];
            float a2 = cf[(eo + 2) * 4 + head], a3 = cf[(eo + 3) * 4 + head];
            float4 h0 = H4[s0 * 32 + lane];
            float4 h1 = H4[s1 * 32 + lane];
            float4 h2 = H4[s2 * 32 + lane];
            float4 h3 = H4[s3 * 32 + lane];
            acc.x = fmaf(a0, h0.x, acc.x); acc.y = fmaf(a0, h0.y, acc.y);
            acc.z = fmaf(a0, h0.z, acc.z); acc.w = fmaf(a0, h0.w, acc.w);
            acc.x = fmaf(a1, h1.x, acc.x); acc.y = fmaf(a1, h1.y, acc.y);
            acc.z = fmaf(a1, h1.z, acc.z); acc.w = fmaf(a1, h1.w, acc.w);
            acc.x = fmaf(a2, h2.x, acc.x); acc.y = fmaf(a2, h2.y, acc.y);
            acc.z = fmaf(a2, h2.z, acc.z); acc.w = fmaf(a2, h2.w, acc.w);
            acc.x = fmaf(a3, h3.x, acc.x); acc.y = fmaf(a3, h3.y, acc.y);
            acc.z = fmaf(a3, h3.z, acc.z); acc.w = fmaf(a3, h3.w, acc.w);
        }
        for (; eo < deg; eo++) {
            int s = ssm[wl][eo];
            float a = cf[eo * 4 + head];
            float4 hv = H4[s * 32 + lane];
            acc.x = fmaf(a, hv.x, acc.x); acc.y = fmaf(a, hv.y, acc.y);
            acc.z = fmaf(a, hv.z, acc.z); acc.w = fmaf(a, hv.w, acc.w);
        }
    } else {
        float psum = 0.f;
        for (int eo = lane & 7; eo < deg; eo += 8) {
            int src = g_sedge[beg + eo].x;
            psum += fexp(lrelu(g_asrc[src * 4 + head] + adh));
        }
        psum += __shfl_xor_sync(0xffffffffu, psum, 1);
        psum += __shfl_xor_sync(0xffffffffu, psum, 2);
        psum += __shfl_xor_sync(0xffffffffu, psum, 4);
        float inv = 1.f / psum;
        for (int eo = 0; eo < deg; eo++) {
            int2 se = g_sedge[beg + eo];
            float ev = fexp(lrelu(g_asrc[se.x * 4 + head] + adh));
            float alpha = ev * inv;
            float4 hv = H4[se.x * 32 + lane];
            acc.x = fmaf(alpha, hv.x, acc.x); acc.y = fmaf(alpha, hv.y, acc.y);
            acc.z = fmaf(alpha, hv.z, acc.z); acc.w = fmaf(alpha, hv.w, acc.w);
            if (WRITE_ALPHA && (lane & 7) == 0)
                alpha_out[(size_t)se.y * 4 + head] = alpha;
        }
    }

    float4 b = *reinterpret_cast<const float4*>(bias + lane * 4);
    acc.x += b.x; acc.y += b.y; acc.z += b.z; acc.w += b.w;
    acc.x = acc.x > 0.f ? acc.x : expm1f(acc.x);
    acc.y = acc.y > 0.f ? acc.y : expm1f(acc.y);
    acc.z = acc.z > 0.f ? acc.z : expm1f(acc.z);
    acc.w = acc.w > 0.f ? acc.w : expm1f(acc.w);
    *reinterpret_cast<float4*>(Xout + w * 128 + lane * 4) = acc;
}

// ---------------- edge kernel, 1 head x 32 ch (final layer) ----------------
__global__ void k_edge1(const float* __restrict__ H2, const float* __restrict__ bias,
                        float* __restrict__ Out) {
    __shared__ float cache[8][CACHE_MAX];
    __shared__ int   ssm[8][CACHE_MAX];
    int wl = threadIdx.x >> 5;
    int lane = threadIdx.x & 31;
    int w = (blockIdx.x * blockDim.x + threadIdx.x) >> 5;
    if (w >= Nn) return;
    int beg = g_rowptr[w];
    int deg = g_rowptr[w + 1] - beg;
    float adv = g_ad2[w];
    float acc = 0.f;

    if (deg <= CACHE_MAX) {
        float psum = 0.f;
        for (int eo = lane; eo < deg; eo += 32) {
            int src = g_sedge[beg + eo].x;
            ssm[wl][eo] = src;
            float ev = fexp(lrelu(__ldg(g_as2 + src) + adv));
            cache[wl][eo] = ev;
            psum += ev;
        }
        #pragma unroll
        for (int o = 16; o; o >>= 1) psum += __shfl_xor_sync(0xffffffffu, psum, o);
        float inv = 1.f / psum;
        for (int eo = lane; eo < deg; eo += 32) cache[wl][eo] *= inv;
        __syncwarp();
        int eo = 0;
        for (; eo + 4 <= deg; eo += 4) {
            int s0 = ssm[wl][eo], s1 = ssm[wl][eo + 1];
            int s2 = ssm[wl][eo + 2], s3 = ssm[wl][eo + 3];
            float a0 = cache[wl][eo],     a1 = cache[wl][eo + 1];
            float a2 = cache[wl][eo + 2], a3 = cache[wl][eo + 3];
            float h0 = H2[s0 * 32 + lane];
            float h1 = H2[s1 * 32 + lane];
            float h2 = H2[s2 * 32 + lane];
            float h3 = H2[s3 * 32 + lane];
            acc = fmaf(a0, h0, acc);
            acc = fmaf(a1, h1, acc);
            acc = fmaf(a2, h2, acc);
            acc = fmaf(a3, h3, acc);
        }
        for (; eo < deg; eo++)
            acc = fmaf(cache[wl][eo], H2[ssm[wl][eo] * 32 + lane], acc);
    } else {
        float psum = 0.f;
        for (int eo = lane; eo < deg; eo += 32) {
            int src = g_sedge[beg + eo].x;
            psum += fexp(lrelu(g_as2[src] + adv));
        }
        #pragma unroll
        for (int o = 16; o; o >>= 1) psum += __shfl_xor_sync(0xffffffffu, psum, o);
        float inv = 1.f / psum;
        for (int eo = 0; eo < deg; eo++) {
            int src = g_sedge[beg + eo].x;
            float ev = fexp(lrelu(g_as2[src] + adv));
            acc = fmaf(ev * inv, H2[src * 32 + lane], acc);
        }
    }
    Out[w * 32 + lane] = acc + bias[lane];
}

// ---------------- launch ----------------
extern "C" void kernel_launch(void* const* d_in, const int* in_sizes, int n_in,
                              void* d_out, int out_size) {
    const float* x   = (const float*)d_in[0];
    const int*   ei  = (const int*)  d_in[1];
    const float* W0  = (const float*)d_in[2];
    const float* as0 = (const float*)d_in[3];
    const float* ad0 = (const float*)d_in[4];
    const float* b0  = (const float*)d_in[5];
    const float* W1  = (const float*)d_in[6];
    const float* as1 = (const float*)d_in[7];
    const float* ad1 = (const float*)d_in[8];
    const float* b1  = (const float*)d_in[9];
    const float* W2  = (const float*)d_in[10];
    const float* as2 = (const float*)d_in[11];
    const float* ad2 = (const float*)d_in[12];
    const float* b2  = (const float*)d_in[13];

    float* out        = (float*)d_out;
    float* alpha0_out = out;                        // [EP, 4]
    float* final_out  = out + (size_t)EP * 4;       // [Nn, 32]

    float *p_h, *p_x1, *p_h2;
    cudaGetSymbolAddress((void**)&p_h,  g_h);
    cudaGetSymbolAddress((void**)&p_x1, g_x1);
    cudaGetSymbolAddress((void**)&p_h2, g_h2);

    static_assert(sizeof(float) == 4, "");
    const int GEMM128_SMEM = 128 * 128 * 4 + 64 * 129 * 4;   // 98560 B
    cudaFuncSetAttribute(k_gemm128, cudaFuncAttributeMaxDynamicSharedMemorySize,
                         GEMM128_SMEM);

    // CSR by destination
    k_zero   <<<(Nn + 255) / 256, 256>>>();
    k_hist   <<<(EP + 255) / 256, 256>>>(ei);
    k_scan   <<<NB_SCAN, 1024>>>();
    k_scatter<<<(EP + 255) / 256, 256>>>(ei);

    // layer 0
    k_gemm128<<<(Nn + 63) / 64, 256, GEMM128_SMEM>>>(x, W0, p_h, as0, ad0);
    k_edge4<true><<<(Nn + 7) / 8, 256>>>(p_h, b0, p_x1, alpha0_out);

    // layer 1
    k_gemm128<<<(Nn + 63) / 64, 256, GEMM128_SMEM>>>(p_x1, W1, p_h, as1, ad1);
    k_edge4<false><<<(Nn + 7) / 8, 256>>>(p_h, b1, p_x1, nullptr);

    // layer 2
    k_gemm32<<<(Nn + 63) / 64, 512>>>(p_x1, W2, p_h2, as2, ad2);
    k_edge1<<<(Nn + 7) / 8, 256>>>(p_h2, b2, final_out);
}

// round 4
// speedup vs baseline: 1.5073x; 1.0040x over previous
#include <cuda_runtime.h>
#include <math.h>
#include <stdint.h>

#define Nn 50000
#define Ee 1600000
#define EP 1650000          // Ee + Nn self loops
#define CACHE_MAX 128       // per-node cached slots (deg ~ Poisson(33); P(deg>128) ~ 0)
#define NB_SCAN 49          // ceil(Nn/1024)

// ---------------- device scratch (static, no allocation) ----------------
__device__ int   g_deg[Nn];
__device__ int   g_off[Nn];
__device__ int   g_rowptr[Nn + 1];
__device__ int2  g_sedge[EP];          // (src, edge_id) packed
__device__ int   g_flag[64];           // lookback flags: (aggregate<<1)|1
__device__ float g_h [Nn * 128];
__device__ float g_x1[Nn * 128];
__device__ float g_h2[Nn * 32];
__device__ float g_asrc[Nn * 4];
__device__ float g_adst[Nn * 4];
__device__ float g_as2[Nn];
__device__ float g_ad2[Nn];

// ---------------- helpers ----------------
__device__ __forceinline__ float lrelu(float x) { return x > 0.f ? x : 0.2f * x; }

// FMA-only exp (no MUFU). Valid for x <= ~30; clamps below -80 (result ~0).
__device__ __forceinline__ float fexp(float x) {
    x = fmaxf(x, -80.0f);
    float t = x * 1.4426950408889634f;
    float r = t + 12582912.0f;                 // round-to-nearest via magic number
    int   n = __float_as_int(r) - 0x4B400000;
    float f = t - (r - 12582912.0f);           // f in [-0.5, 0.5]
    float p = 0.0013333558f;
    p = fmaf(p, f, 0.0096181291f);
    p = fmaf(p, f, 0.0555041087f);
    p = fmaf(p, f, 0.2402265070f);
    p = fmaf(p, f, 0.6931471806f);
    p = fmaf(p, f, 1.0f);
    return __int_as_float((n + 127) << 23) * p;
}

__device__ __forceinline__ void ffma2(unsigned long long& d, unsigned long long a,
                                      unsigned long long b) {
    asm("fma.rn.f32x2 %0, %1, %2, %0;" : "+l"(d) : "l"(a), "l"(b));
}
__device__ __forceinline__ unsigned long long pack2(float v) {
    unsigned long long p;
    asm("mov.b64 %0, {%1, %1};" : "=l"(p) : "r"(__float_as_uint(v)));
    return p;
}

// ---------------- CSR build ----------------
__global__ void k_zero() {
    int i = blockIdx.x * blockDim.x + threadIdx.x;
    if (i < Nn) g_deg[i] = 0;
    if (i < 64) g_flag[i] = 0;
}

__global__ void k_hist(const int* __restrict__ ei) {
    int e = blockIdx.x * blockDim.x + threadIdx.x;
    if (e >= EP) return;
    int dst = (e < Ee) ? ei[Ee + e] : (e - Ee);
    atomicAdd(&g_deg[dst], 1);
}

// single-pass exclusive scan with decoupled lookback (49 blocks, all resident)
__global__ void k_scan() {
    __shared__ int warp_sums[32];
    __shared__ int s_prev;
    int tid = threadIdx.x, lane = tid & 31, wid = tid >> 5;
    int b = blockIdx.x;
    int i = b * 1024 + tid;
    int v = (i < Nn) ? g_deg[i] : 0;
    int incl = v;
    #pragma unroll
    for (int o = 1; o < 32; o <<= 1) {
        int t = __shfl_up_sync(0xffffffffu, incl, o);
        if (lane >= o) incl += t;
    }
    if (lane == 31) warp_sums[wid] = incl;
    __syncthreads();
    if (wid == 0) {
        int ws = warp_sums[lane];
        int wi = ws;
        #pragma unroll
        for (int o = 1; o < 32; o <<= 1) {
            int t = __shfl_up_sync(0xffffffffu, wi, o);
            if (lane >= o) wi += t;
        }
        warp_sums[lane] = wi - ws;   // exclusive warp base
    }
    __syncthreads();
    int excl = incl - v + warp_sums[wid];
    // publish block aggregate ASAP (value<<1 | 1); aggregates < 2^22 so no overflow
    if (tid == 1023) atomicExch(&g_flag[b], ((excl + v) << 1) | 1);
    // lookback: warp 0 sums aggregates of all previous blocks
    if (wid == 0) {
        int sum = 0;
        for (int base = 0; base < b; base += 32) {
            int j = base + lane;
            int f = 0;
            if (j < b) {
                do { f = atomicOr(&g_flag[j], 0); } while (!(f & 1));
                sum += (f >> 1);
            }
        }
        #pragma unroll
        for (int o = 16; o; o >>= 1) sum += __shfl_xor_sync(0xffffffffu, sum, o);
        if (lane == 0) s_prev = sum;
    }
    __syncthreads();
    if (i < Nn) {
        g_rowptr[i] = excl + s_prev;
        g_off[i] = 0;
    }
    if (b == 0 && tid == 0) g_rowptr[Nn] = EP;
}

__global__ void k_scatter(const int* __restrict__ ei) {
    int e = blockIdx.x * blockDim.x + threadIdx.x;
    if (e >= EP) return;
    int src, dst;
    if (e < Ee) { src = ei[e]; dst = ei[Ee + e]; }
    else        { src = dst = e - Ee; }
    int pos = g_rowptr[dst] + atomicAdd(&g_off[dst], 1);
    g_sedge[pos] = make_int2(src, e);
}

// ---------------- GEMM 128x128, W staged in SMEM, fused alpha epilogue ----------
// Y[N,128] = X[N,128] @ W[128,128]; also writes g_asrc/g_adst (per-head dots).
// Block: 256 threads, 64-row tile. Thread: 4 rows x 8 cols (4 packed pairs).
// Dynamic SMEM: ws[128*128] (64KB) + xs[64][129] (33KB).
__global__ void k_gemm128(const float* __restrict__ X, const float* __restrict__ W,
                          float* __restrict__ Y,
                          const float* __restrict__ as, const float* __restrict__ ad) {
    extern __shared__ float dyn[];
    float* ws = dyn;                               // [128][128]
    float (*xs)[129] = reinterpret_cast<float (*)[129]>(dyn + 128 * 128);
    int ct = threadIdx.x & 15, rt = threadIdx.x >> 4;
    int lane = threadIdx.x & 31;
    int row0 = blockIdx.x * 64;
    // stage W (64KB) via float4
    for (int idx = threadIdx.x; idx < 128 * 32; idx += 256)
        reinterpret_cast<float4*>(ws)[idx] = reinterpret_cast<const float4*>(W)[idx];
    // stage X tile
    for (int idx = threadIdx.x; idx < 64 * 128; idx += 256) {
        int r = idx >> 7, c = idx & 127;
        int gr = row0 + r;
        xs[r][c] = (gr < Nn) ? X[gr * 128 + c] : 0.f;
    }
    __syncthreads();
    int r0 = rt * 4, c0 = ct * 8;
    unsigned long long acc[4][4];
    #pragma unroll
    for (int r = 0; r < 4; r++)
        #pragma unroll
        for (int c = 0; c < 4; c++) acc[r][c] = 0ull;

    const float* wsc = ws + c0;
    #pragma unroll 2
    for (int k = 0; k < 128; k++) {
        ulonglong2 wa = *reinterpret_cast<const ulonglong2*>(wsc + k * 128);
        ulonglong2 wb = *reinterpret_cast<const ulonglong2*>(wsc + k * 128 + 4);
        #pragma unroll
        for (int r = 0; r < 4; r++) {
            unsigned long long xp = pack2(xs[r0 + r][k]);
            ffma2(acc[r][0], xp, wa.x);
            ffma2(acc[r][1], xp, wa.y);
            ffma2(acc[r][2], xp, wb.x);
            ffma2(acc[r][3], xp, wb.y);
        }
    }
    // per-thread as/ad slice (8 cols, all within one head)
    float asv[8], adv[8];
    #pragma unroll
    for (int c = 0; c < 8; c++) { asv[c] = as[c0 + c]; adv[c] = ad[c0 + c]; }
    int head = ct >> 2;

    #pragma unroll
    for (int r = 0; r < 4; r++) {
        int gr = row0 + r0 + r;
        float o[8];
        #pragma unroll
        for (int c = 0; c < 4; c++)
            asm("mov.b64 {%0, %1}, %2;" : "=f"(o[2 * c]), "=f"(o[2 * c + 1]) : "l"(acc[r][c]));
        if (gr < Nn) {
            *reinterpret_cast<float4*>(Y + (size_t)gr * 128 + c0) =
                make_float4(o[0], o[1], o[2], o[3]);
            *reinterpret_cast<float4*>(Y + (size_t)gr * 128 + c0 + 4) =
                make_float4(o[4], o[5], o[6], o[7]);
        }
        // fused alpha: per-head dot over 32 cols = 4 lanes x 8 cols
        float psA = 0.f, psD = 0.f;
        #pragma unroll
        for (int c = 0; c < 8; c++) {
            psA = fmaf(o[c], asv[c], psA);
            psD = fmaf(o[c], adv[c], psD);
        }
        psA += __shfl_xor_sync(0xffffffffu, psA, 1);
        psA += __shfl_xor_sync(0xffffffffu, psA, 2);
        psD += __shfl_xor_sync(0xffffffffu, psD, 1);
        psD += __shfl_xor_sync(0xffffffffu, psD, 2);
        if ((lane & 3) == 0 && gr < Nn) {
            g_asrc[gr * 4 + head] = psA;
            g_adst[gr * 4 + head] = psD;
        }
    }
}

// ---------------- GEMM: Y[N,32] = X[N,128] @ W[128,32], fused alpha1 ----------
__global__ void k_gemm32(const float* __restrict__ X, const float* __restrict__ W,
                         float* __restrict__ Y,
                         const float* __restrict__ as, const float* __restrict__ ad) {
    constexpr int CG = 8;             // col groups of 4
    constexpr int RT = 64;            // rows per tile
    __shared__ float xs[RT][129];
    __shared__ float wsm[128 * 32];
    int tx = threadIdx.x % CG;
    int ty = threadIdx.x / CG;
    int lane = threadIdx.x & 31;
    int row0 = blockIdx.x * RT;
    for (int idx = threadIdx.x; idx < 128 * 8; idx += 512)
        reinterpret_cast<float4*>(wsm)[idx] = reinterpret_cast<const float4*>(W)[idx];
    for (int idx = threadIdx.x; idx < RT * 128; idx += 512) {
        int r = idx >> 7, c = idx & 127;
        int gr = row0 + r;
        xs[r][c] = (gr < Nn) ? X[gr * 128 + c] : 0.f;
    }
    __syncthreads();
    float4 acc = make_float4(0.f, 0.f, 0.f, 0.f);
    #pragma unroll 16
    for (int k = 0; k < 128; k++) {
        float xv = xs[ty][k];
        float4 w4 = *reinterpret_cast<const float4*>(wsm + k * 32 + tx * 4);
        acc.x = fmaf(xv, w4.x, acc.x);
        acc.y = fmaf(xv, w4.y, acc.y);
        acc.z = fmaf(xv, w4.z, acc.z);
        acc.w = fmaf(xv, w4.w, acc.w);
    }
    int gr = row0 + ty;
    if (gr < Nn)
        *reinterpret_cast<float4*>(Y + gr * 32 + tx * 4) = acc;
    // fused alpha1: dot over 32 cols = 8 lanes x 4 cols
    float4 a4 = *reinterpret_cast<const float4*>(as + tx * 4);
    float4 d4 = *reinterpret_cast<const float4*>(ad + tx * 4);
    float psA = acc.x * a4.x + acc.y * a4.y + acc.z * a4.z + acc.w * a4.w;
    float psD = acc.x * d4.x + acc.y * d4.y + acc.z * d4.z + acc.w * d4.w;
    #pragma unroll
    for (int o = 4; o; o >>= 1) {
        psA += __shfl_xor_sync(0xffffffffu, psA, o);
        psD += __shfl_xor_sync(0xffffffffu, psD, o);
    }
    if ((lane & 7) == 0 && gr < Nn) { g_as2[gr] = psA; g_ad2[gr] = psD; }
}

// ---------------- edge kernel, 4 heads x 32 ch (one warp per dst) ----------------
template<bool WRITE_ALPHA>
__global__ void k_edge4(const float* __restrict__ H, const float* __restrict__ bias,
                        float* __restrict__ Xout, float* __restrict__ alpha_out) {
    __shared__ float4 cache4[8][CACHE_MAX];   // 16 KB (alpha per edge, 4 heads)
    __shared__ int    ssm[8][CACHE_MAX];      //  4 KB (src per edge)
    int wl = threadIdx.x >> 5;
    int lane = threadIdx.x & 31;
    int w = (blockIdx.x * blockDim.x + threadIdx.x) >> 5;
    if (w >= Nn) return;
    int beg = g_rowptr[w];
    int deg = g_rowptr[w + 1] - beg;
    float4 adv = *reinterpret_cast<const float4*>(g_adst + 4 * w);
    int head = lane >> 3;
    float adh = head == 0 ? adv.x : head == 1 ? adv.y : head == 2 ? adv.z : adv.w;
    float* cf = reinterpret_cast<float*>(cache4[wl]);
    const float4* H4 = reinterpret_cast<const float4*>(H);
    float4 acc = make_float4(0.f, 0.f, 0.f, 0.f);

    if (deg <= CACHE_MAX) {
        for (int eo = lane; eo < deg; eo += 32)
            ssm[wl][eo] = g_sedge[beg + eo].x;
        __syncwarp();
        float psum = 0.f;
        for (int eo = lane & 7; eo < deg; eo += 8) {
            int src = ssm[wl][eo];
            float ev = fexp(lrelu(__ldg(g_asrc + src * 4 + head) + adh));
            cf[eo * 4 + head] = ev;
            psum += ev;
        }
        psum += __shfl_xor_sync(0xffffffffu, psum, 1);
        psum += __shfl_xor_sync(0xffffffffu, psum, 2);
        psum += __shfl_xor_sync(0xffffffffu, psum, 4);
        float inv = 1.f / psum;
        for (int eo = lane & 7; eo < deg; eo += 8)
            cf[eo * 4 + head] *= inv;                 // cache now holds alpha
        __syncwarp();
        if (WRITE_ALPHA) {
            for (int eo = lane; eo < deg; eo += 32) {
                int eid = g_sedge[beg + eo].y;
                *reinterpret_cast<float4*>(alpha_out + (size_t)eid * 4) = cache4[wl][eo];
            }
        }
        int eo = 0;
        for (; eo + 4 <= deg; eo += 4) {
            int s0 = ssm[wl][eo], s1 = ssm[wl][eo + 1];
            int s2 = ssm[wl][eo + 2], s3 = ssm[wl][eo + 3];
            float a0 = cf[eo * 4 + head],       a1 = cf[(eo + 1) * 4 + head];
            float a2 = cf[(eo + 2) * 4 + head], a3 = cf[(eo + 3) * 4 + head];
            float4 h0 = H4[s0 * 32 + lane];
            float4 h1 = H4[s1 * 32 + lane];
            float4 h2 = H4[s2 * 32 + lane];
            float4 h3 = H4[s3 * 32 + lane];
            acc.x = fmaf(a0, h0.x, acc.x); acc.y = fmaf(a0, h0.y, acc.y);
            acc.z = fmaf(a0, h0.z, acc.z); acc.w = fmaf(a0, h0.w, acc.w);
            acc.x = fmaf(a1, h1.x, acc.x); acc.y = fmaf(a1, h1.y, acc.y);
            acc.z = fmaf(a1, h1.z, acc.z); acc.w = fmaf(a1, h1.w, acc.w);
            acc.x = fmaf(a2, h2.x, acc.x); acc.y = fmaf(a2, h2.y, acc.y);
            acc.z = fmaf(a2, h2.z, acc.z); acc.w = fmaf(a2, h2.w, acc.w);
            acc.x = fmaf(a3, h3.x, acc.x); acc.y = fmaf(a3, h3.y, acc.y);
            acc.z = fmaf(a3, h3.z, acc.z); acc.w = fmaf(a3, h3.w, acc.w);
        }
        for (; eo < deg; eo++) {
            int s = ssm[wl][eo];
            float a = cf[eo * 4 + head];
            float4 hv = H4[s * 32 + lane];
            acc.x = fmaf(a, hv.x, acc.x); acc.y = fmaf(a, hv.y, acc.y);
            acc.z = fmaf(a, hv.z, acc.z); acc.w = fmaf(a, hv.w, acc.w);
        }
    } else {
        float psum = 0.f;
        for (int eo = lane & 7; eo < deg; eo += 8) {
            int src = g_sedge[beg + eo].x;
            psum += fexp(lrelu(g_asrc[src * 4 + head] + adh));
        }
        psum += __shfl_xor_sync(0xffffffffu, psum, 1);
        psum += __shfl_xor_sync(0xffffffffu, psum, 2);
        psum += __shfl_xor_sync(0xffffffffu, psum, 4);
        float inv = 1.f / psum;
        for (int eo = 0; eo < deg; eo++) {
            int2 se = g_sedge[beg + eo];
            float ev = fexp(lrelu(g_asrc[se.x * 4 + head] + adh));
            float alpha = ev * inv;
            float4 hv = H4[se.x * 32 + lane];
            acc.x = fmaf(alpha, hv.x, acc.x); acc.y = fmaf(alpha, hv.y, acc.y);
            acc.z = fmaf(alpha, hv.z, acc.z); acc.w = fmaf(alpha, hv.w, acc.w);
            if (WRITE_ALPHA && (lane & 7) == 0)
                alpha_out[(size_t)se.y * 4 + head] = alpha;
        }
    }

    float4 b = *reinterpret_cast<const float4*>(bias + lane * 4);
    acc.x += b.x; acc.y += b.y; acc.z += b.z; acc.w += b.w;
    acc.x = acc.x > 0.f ? acc.x : expm1f(acc.x);
    acc.y = acc.y > 0.f ? acc.y : expm1f(acc.y);
    acc.z = acc.z > 0.f ? acc.z : expm1f(acc.z);
    acc.w = acc.w > 0.f ? acc.w : expm1f(acc.w);
    *reinterpret_cast<float4*>(Xout + w * 128 + lane * 4) = acc;
}

// ---------------- edge kernel, 1 head x 32 ch (final layer) ----------------
__global__ void k_edge1(const float* __restrict__ H2, const float* __restrict__ bias,
                        float* __restrict__ Out) {
    __shared__ float cache[8][CACHE_MAX];
    __shared__ int   ssm[8][CACHE_MAX];
    int wl = threadIdx.x >> 5;
    int lane = threadIdx.x & 31;
    int w = (blockIdx.x * blockDim.x + threadIdx.x) >> 5;
    if (w >= Nn) return;
    int beg = g_rowptr[w];
    int deg = g_rowptr[w + 1] - beg;
    float adv = g_ad2[w];
    float acc = 0.f;

    if (deg <= CACHE_MAX) {
        float psum = 0.f;
        for (int eo = lane; eo < deg; eo += 32) {
            int src = g_sedge[beg + eo].x;
            ssm[wl][eo] = src;
            float ev = fexp(lrelu(__ldg(g_as2 + src) + adv));
            cache[wl][eo] = ev;
            psum += ev;
        }
        #pragma unroll
        for (int o = 16; o; o >>= 1) psum += __shfl_xor_sync(0xffffffffu, psum, o);
        float inv = 1.f / psum;
        for (int eo = lane; eo < deg; eo += 32) cache[wl][eo] *= inv;
        __syncwarp();
        int eo = 0;
        for (; eo + 4 <= deg; eo += 4) {
            int s0 = ssm[wl][eo], s1 = ssm[wl][eo + 1];
            int s2 = ssm[wl][eo + 2], s3 = ssm[wl][eo + 3];
            float a0 = cache[wl][eo],     a1 = cache[wl][eo + 1];
            float a2 = cache[wl][eo + 2], a3 = cache[wl][eo + 3];
            float h0 = H2[s0 * 32 + lane];
            float h1 = H2[s1 * 32 + lane];
            float h2 = H2[s2 * 32 + lane];
            float h3 = H2[s3 * 32 + lane];
            acc = fmaf(a0, h0, acc);
            acc = fmaf(a1, h1, acc);
            acc = fmaf(a2, h2, acc);
            acc = fmaf(a3, h3, acc);
        }
        for (; eo < deg; eo++)
            acc = fmaf(cache[wl][eo], H2[ssm[wl][eo] * 32 + lane], acc);
    } else {
        float psum = 0.f;
        for (int eo = lane; eo < deg; eo += 32) {
            int src = g_sedge[beg + eo].x;
            psum += fexp(lrelu(g_as2[src] + adv));
        }
        #pragma unroll
        for (int o = 16; o; o >>= 1) psum += __shfl_xor_sync(0xffffffffu, psum, o);
        float inv = 1.f / psum;
        for (int eo = 0; eo < deg; eo++) {
            int src = g_sedge[beg + eo].x;
            float ev = fexp(lrelu(g_as2[src] + adv));
            acc = fmaf(ev * inv, H2[src * 32 + lane], acc);
        }
    }
    Out[w * 32 + lane] = acc + bias[lane];
}

// ---------------- launch ----------------
extern "C" void kernel_launch(void* const* d_in, const int* in_sizes, int n_in,
                              void* d_out, int out_size) {
    const float* x   = (const float*)d_in[0];
    const int*   ei  = (const int*)  d_in[1];
    const float* W0  = (const float*)d_in[2];
    const float* as0 = (const float*)d_in[3];
    const float* ad0 = (const float*)d_in[4];
    const float* b0  = (const float*)d_in[5];
    const float* W1  = (const float*)d_in[6];
    const float* as1 = (const float*)d_in[7];
    const float* ad1 = (const float*)d_in[8];
    const float* b1  = (const float*)d_in[9];
    const float* W2  = (const float*)d_in[10];
    const float* as2 = (const float*)d_in[11];
    const float* ad2 = (const float*)d_in[12];
    const float* b2  = (const float*)d_in[13];

    float* out        = (float*)d_out;
    float* alpha0_out = out;                        // [EP, 4]
    float* final_out  = out + (size_t)EP * 4;       // [Nn, 32]

    float *p_h, *p_x1, *p_h2;
    cudaGetSymbolAddress((void**)&p_h,  g_h);
    cudaGetSymbolAddress((void**)&p_x1, g_x1);
    cudaGetSymbolAddress((void**)&p_h2, g_h2);

    static_assert(sizeof(float) == 4, "");
    const int GEMM128_SMEM = 128 * 128 * 4 + 64 * 129 * 4;   // 98560 B
    cudaFuncSetAttribute(k_gemm128, cudaFuncAttributeMaxDynamicSharedMemorySize,
                         GEMM128_SMEM);

    // CSR by destination
    k_zero   <<<(Nn + 255) / 256, 256>>>();
    k_hist   <<<(EP + 255) / 256, 256>>>(ei);
    k_scan   <<<NB_SCAN, 1024>>>();
    k_scatter<<<(EP + 255) / 256, 256>>>(ei);

    // layer 0
    k_gemm128<<<(Nn + 63) / 64, 256, GEMM128_SMEM>>>(x, W0, p_h, as0, ad0);
    k_edge4<true><<<(Nn + 7) / 8, 256>>>(p_h, b0, p_x1, alpha0_out);

    // layer 1
    k_gemm128<<<(Nn + 63) / 64, 256, GEMM128_SMEM>>>(p_x1, W1, p_h, as1, ad1);
    k_edge4<false><<<(Nn + 7) / 8, 256>>>(p_h, b1, p_x1, nullptr);

    // layer 2
    k_gemm32<<<(Nn + 63) / 64, 512>>>(p_x1, W2, p_h2, as2, ad2);
    k_edge1<<<(Nn + 7) / 8, 256>>>(p_h2, b2, final_out);
}